// round 9
// baseline (speedup 1.0000x reference)
#include <cuda_runtime.h>
#include <math.h>

// Problem shape (fixed by the reference's setup_inputs)
#define Bn 4
#define Tn 8192
#define Dn 1024
#define D4n (Dn / 4)       // 256 float4 groups across channels
#define Ln 32              // chunk length along time
#define Cn (Tn / Ln)       // 256 chunks
#define CPL 8              // chunks per lane in the warp scan
#define NTH 131072             // threads = items per half (Cn * 2 * D4n)
#define GRID_CTAS (NTH / 256)  // 512 CTAs -> all co-resident (4/SM cap)

// Per-channel tables (double closed form, computed in k_setup):
__device__ float2 g_r [Dn];      // r = exp(-|a|)(cos f, sin f)
__device__ float2 g_rL[Dn];      // r^L
__device__ float2 g_w [5][Dn];   // r^(8L * 2^s)

// Scratch (L2-resident): chunk-end and carry-in states, [c][b][k][d4].
__device__ float2 g_ends [Cn * Bn * 4 * D4n];
__device__ float2 g_carry[Cn * Bn * 4 * D4n];

// Software grid barrier slots (reset each launch by k_setup).
__device__ int g_bar[5];

// ---------------------------------------------------------------------------
// setup: one (exp,cos,sin) double triple per thread; 7*Dn = 7168 threads.
// job j: 0 -> g_r, 1 -> g_rL, 2..6 -> g_w[j-2]. Thread 0 resets barriers.
// ---------------------------------------------------------------------------
__global__ void k_setup(const float* __restrict__ decay,
                        const float* __restrict__ freq)
{
    int tid = blockIdx.x * blockDim.x + threadIdx.x;
    if (tid < 5) g_bar[tid] = 0;
    if (tid >= 7 * Dn) return;
    int d = tid % Dn;
    int j = tid / Dn;

    double span;
    if (j == 0)      span = 1.0;
    else if (j == 1) span = (double)Ln;
    else             span = (double)(CPL * Ln * (1 << (j - 2)));

    double a = fabs((double)decay[d]);
    double f = (double)freq[d];
    double g = exp(-a * span);
    float2 v = make_float2((float)(g * cos(f * span)),
                           (float)(g * sin(f * span)));

    if (j == 0)      g_r[d]      = v;
    else if (j == 1) g_rL[d]     = v;
    else             g_w[j-2][d] = v;
}

// ---------------------------------------------------------------------------
__device__ __forceinline__ void gsync(int slot)
{
    __syncthreads();
    if (threadIdx.x == 0) {
        __threadfence();                       // release prior writes
        atomicAdd(&g_bar[slot], 1);
        volatile int* bp = &g_bar[slot];
        while (*bp < GRID_CTAS) { }
        __threadfence();                       // acquire
    }
    __syncthreads();
}

// ---------------------------------------------------------------------------
// Fused, batch-split: for half h (b in {2h, 2h+1}):
//   phase1 (local recurrences; x_h becomes L2-resident)
//   gsync | phase2 (warp scan over chunks) | gsync
//   phase3 (replay; x_h re-read from L2, y streamed out with stcs)
// Per phase, each thread owns exactly one (c, b, d4) item of its half.
// ---------------------------------------------------------------------------
__global__ __launch_bounds__(256, 4)
void k_fused(const float4* __restrict__ x, float4* __restrict__ y)
{
    const int t = blockIdx.x * blockDim.x + threadIdx.x;
    const int d4 = t % D4n;
    const int bb = (t / D4n) & 1;          // sub-batch within half
    const int c  = t / (2 * D4n);          // chunk index 0..Cn-1

    // per-step rotation r for this thread's 4 channels
    const float4* rp = (const float4*)g_r;
    float4 r01 = rp[2 * d4], r23 = rp[2 * d4 + 1];
    float rre[4] = {r01.x, r01.z, r23.x, r23.z};
    float rim[4] = {r01.y, r01.w, r23.y, r23.w};

#pragma unroll 1
    for (int h = 0; h < 2; h++) {
        const int b = 2 * h + bb;
        const float4* xp = x + (size_t)(b * Tn + c * Ln) * D4n + d4;
        float4*       yp = y + (size_t)(b * Tn + c * Ln) * D4n + d4;

        // -------- phase 1: local recurrence, zero init --------
        {
            float zre[4] = {0.f, 0.f, 0.f, 0.f};
            float zim[4] = {0.f, 0.f, 0.f, 0.f};
#pragma unroll 8
            for (int j = 0; j < Ln; j++) {
                float4 xv = xp[(size_t)j * D4n];
                float xr[4] = {xv.x, xv.y, xv.z, xv.w};
#pragma unroll
                for (int k = 0; k < 4; k++) {
                    float nre = fmaf(rre[k], zre[k], fmaf(-rim[k], zim[k], xr[k]));
                    float nim = fmaf(rre[k], zim[k], rim[k] * zre[k]);
                    zre[k] = nre;
                    zim[k] = nim;
                }
            }
#pragma unroll
            for (int k = 0; k < 4; k++)
                g_ends[((c * Bn + b) * 4 + k) * D4n + d4] =
                    make_float2(zre[k], zim[k]);
        }

        gsync(2 * h + 0);

        // -------- phase 2: warp-parallel scan (2048 active warps) --------
        {
            const int wid  = t >> 5;
            const int lane = t & 31;
            if (wid < 2 * Dn) {
                const int d  = wid % Dn;
                const int b2 = 2 * h + (wid / Dn);
                const int sd4 = d >> 2;
                const int sk  = d & 3;

                float2 rL = g_rL[d];
                float rLre = rL.x, rLim = rL.y;

                float2 e[CPL];
                float Are = 0.0f, Aim = 0.0f;
#pragma unroll
                for (int i = 0; i < CPL; i++) {
                    int cc = lane * CPL + i;
                    e[i] = g_ends[((cc * Bn + b2) * 4 + sk) * D4n + sd4];
                    float nre = fmaf(rLre, Are, fmaf(-rLim, Aim, e[i].x));
                    float nim = fmaf(rLre, Aim, fmaf(rLim, Are, e[i].y));
                    Are = nre; Aim = nim;
                }

                float Sre = Are, Sim = Aim;
#pragma unroll
                for (int step = 0; step < 5; step++) {
                    int off = 1 << step;
                    float2 w = g_w[step][d];
                    float Pre = __shfl_up_sync(0xFFFFFFFFu, Sre, off);
                    float Pim = __shfl_up_sync(0xFFFFFFFFu, Sim, off);
                    if (lane >= off) {
                        Sre = fmaf(w.x, Pre, fmaf(-w.y, Pim, Sre));
                        Sim = fmaf(w.x, Pim, fmaf(w.y, Pre, Sim));
                    }
                }

                float Cre = __shfl_up_sync(0xFFFFFFFFu, Sre, 1);
                float Cim = __shfl_up_sync(0xFFFFFFFFu, Sim, 1);
                if (lane == 0) { Cre = 0.0f; Cim = 0.0f; }

#pragma unroll
                for (int i = 0; i < CPL; i++) {
                    int cc = lane * CPL + i;
                    g_carry[((cc * Bn + b2) * 4 + sk) * D4n + sd4] =
                        make_float2(Cre, Cim);
                    float nre = fmaf(rLre, Cre, fmaf(-rLim, Cim, e[i].x));
                    float nim = fmaf(rLre, Cim, fmaf(rLim, Cre, e[i].y));
                    Cre = nre; Cim = nim;
                }
            }
        }

        gsync(2 * h + 1);

        // -------- phase 3: replay seeded with carry; x from L2 --------
        {
            float zre[4], zim[4];
#pragma unroll
            for (int k = 0; k < 4; k++) {
                float2 cc = g_carry[((c * Bn + b) * 4 + k) * D4n + d4];
                zre[k] = cc.x;
                zim[k] = cc.y;
            }
#pragma unroll 8
            for (int j = 0; j < Ln; j++) {
                float4 xv = xp[(size_t)j * D4n];
                float xr[4] = {xv.x, xv.y, xv.z, xv.w};
#pragma unroll
                for (int k = 0; k < 4; k++) {
                    float nre = fmaf(rre[k], zre[k], fmaf(-rim[k], zim[k], xr[k]));
                    float nim = fmaf(rre[k], zim[k], rim[k] * zre[k]);
                    zre[k] = nre;
                    zim[k] = nim;
                }
                __stcs(&yp[(size_t)j * D4n],
                       make_float4(zre[0], zre[1], zre[2], zre[3]));
            }
        }

        if (h == 0) gsync(4);   // keep halves phase-aligned (protects L2 set)
    }
}

// ---------------------------------------------------------------------------
extern "C" void kernel_launch(void* const* d_in, const int* in_sizes, int n_in,
                              void* d_out, int out_size)
{
    const float* x     = (const float*)d_in[0];
    const float* decay = (const float*)d_in[1];
    const float* freq  = (const float*)d_in[2];
    float* y = (float*)d_out;

    k_setup<<<(7 * Dn + 255) / 256, 256>>>(decay, freq);
    k_fused<<<GRID_CTAS, 256>>>((const float4*)x, (float4*)y);
}

// round 10
// speedup vs baseline: 1.1589x; 1.1589x over previous
#include <cuda_runtime.h>
#include <math.h>

// Problem shape (fixed by the reference's setup_inputs)
#define Bn 4
#define Tn 8192
#define Dn 1024
#define D4n (Dn / 4)       // 256 float4 groups across channels
#define Ln 32              // chunk length along time
#define Cn (Tn / Ln)       // 256 chunks
#define CPL 8              // chunks per lane in the warp scan
#define NIT (Cn * Bn * D4n)    // 262144 work items
#define NTH (NIT / 2)          // 131072 threads; 2 chunk-rounds per phase
#define GRID_CTAS (NTH / 256)  // 512 CTAs -> all co-resident (4/SM cap)

// Scan tables, computed in-kernel (double closed form) by table-duty threads:
__device__ float2 g_rL[Dn];      // r^L
__device__ float2 g_w [5][Dn];   // r^(8L * 2^s), s = 0..4

// Scratch (L2-resident): chunk-end and carry-in states, [c][b][k][d4]. 8 MB each.
__device__ float2 g_ends [Cn * Bn * 4 * D4n];
__device__ float2 g_carry[Cn * Bn * 4 * D4n];

// Self-resetting ticket barrier (never reset; correct across graph replays).
__device__ unsigned g_bar[2];

// ---------------------------------------------------------------------------
__device__ __forceinline__ void gsync(int slot)
{
    __syncthreads();
    if (threadIdx.x == 0) {
        __threadfence();                               // release prior writes
        unsigned ticket = atomicAdd(&g_bar[slot], 1u);
        unsigned target = (ticket / GRID_CTAS + 1u) * GRID_CTAS;
        volatile unsigned* bp = &g_bar[slot];
        while (*bp < target) { }
        __threadfence();                               // acquire
    }
    __syncthreads();
}

// ---------------------------------------------------------------------------
// Single fused kernel:
//   table duty (t < 6*Dn): one double (exp,cos,sin) triple -> g_rL / g_w
//   phase1: local recurrence per chunk (2 rounds), r computed in fp32
//   gsync | phase2: warp-parallel Kogge-Stone scan over 256 chunks | gsync
//   phase3: replay with carry, reverse round order (x re-read is L2-hot)
// ---------------------------------------------------------------------------
__global__ __launch_bounds__(256, 4)
void k_fused(const float4* __restrict__ x, float4* __restrict__ y,
             const float* __restrict__ decay, const float* __restrict__ freq)
{
    const int t = blockIdx.x * blockDim.x + threadIdx.x;

    // ---- table duty: 6144 threads, one double triple each ----
    if (t < 6 * Dn) {
        int d = t % Dn;
        int j = t / Dn;                       // 0 -> rL, 1..5 -> w[j-1]
        double span = (j == 0) ? (double)Ln
                               : (double)(CPL * Ln * (1 << (j - 1)));
        double a = fabs((double)decay[d]);
        double f = (double)freq[d];
        double g = exp(-a * span);
        float2 v = make_float2((float)(g * cos(f * span)),
                               (float)(g * sin(f * span)));
        if (j == 0) g_rL[d] = v;
        else        g_w[j - 1][d] = v;
    }

    // ---- per-thread step rotation r for 4 channels (fp32 closed form) ----
    const int d4 = t % D4n;
    float rre[4], rim[4];
    {
        const float4* a4p = (const float4*)decay;
        const float4* f4p = (const float4*)freq;
        float4 a4 = a4p[d4];
        float4 f4 = f4p[d4];
        float av[4] = {a4.x, a4.y, a4.z, a4.w};
        float fv[4] = {f4.x, f4.y, f4.z, f4.w};
#pragma unroll
        for (int k = 0; k < 4; k++) {
            float g = expf(-fabsf(av[k]));
            float s, co;
            sincosf(fv[k], &s, &co);
            rre[k] = g * co;
            rim[k] = g * s;
        }
    }

    // ---------------- phase 1: local recurrence per chunk ----------------
#pragma unroll 1
    for (int round = 0; round < 2; round++) {
        const int item = round * NTH + t;
        const int b = (item / D4n) % Bn;
        const int c = item / (D4n * Bn);

        float zre[4] = {0.f, 0.f, 0.f, 0.f};
        float zim[4] = {0.f, 0.f, 0.f, 0.f};
        const float4* xp = x + (size_t)(b * Tn + c * Ln) * D4n + d4;
#pragma unroll 8
        for (int j = 0; j < Ln; j++) {
            float4 xv = xp[(size_t)j * D4n];
            float xr[4] = {xv.x, xv.y, xv.z, xv.w};
#pragma unroll
            for (int k = 0; k < 4; k++) {
                float nre = fmaf(rre[k], zre[k], fmaf(-rim[k], zim[k], xr[k]));
                float nim = fmaf(rre[k], zim[k], rim[k] * zre[k]);
                zre[k] = nre;
                zim[k] = nim;
            }
        }
#pragma unroll
        for (int k = 0; k < 4; k++)
            g_ends[((c * Bn + b) * 4 + k) * D4n + d4] =
                make_float2(zre[k], zim[k]);
    }

    gsync(0);

    // ---------------- phase 2: warp-parallel scan over chunks ----------------
    {
        const int wid  = t >> 5;         // 0 .. Bn*Dn-1  (4096 series)
        const int lane = t & 31;
        const int d = wid % Dn;
        const int b = wid / Dn;
        const int sd4 = d >> 2;
        const int sk  = d & 3;

        float2 rL = g_rL[d];
        float rLre = rL.x, rLim = rL.y;

        float2 e[CPL];
        float Are = 0.0f, Aim = 0.0f;
#pragma unroll
        for (int i = 0; i < CPL; i++) {
            int c = lane * CPL + i;
            e[i] = g_ends[((c * Bn + b) * 4 + sk) * D4n + sd4];
            float nre = fmaf(rLre, Are, fmaf(-rLim, Aim, e[i].x));
            float nim = fmaf(rLre, Aim, fmaf(rLim, Are, e[i].y));
            Are = nre; Aim = nim;
        }

        float Sre = Are, Sim = Aim;
#pragma unroll
        for (int step = 0; step < 5; step++) {
            int off = 1 << step;
            float2 w = g_w[step][d];
            float Pre = __shfl_up_sync(0xFFFFFFFFu, Sre, off);
            float Pim = __shfl_up_sync(0xFFFFFFFFu, Sim, off);
            if (lane >= off) {
                Sre = fmaf(w.x, Pre, fmaf(-w.y, Pim, Sre));
                Sim = fmaf(w.x, Pim, fmaf(w.y, Pre, Sim));
            }
        }

        float Cre = __shfl_up_sync(0xFFFFFFFFu, Sre, 1);
        float Cim = __shfl_up_sync(0xFFFFFFFFu, Sim, 1);
        if (lane == 0) { Cre = 0.0f; Cim = 0.0f; }

#pragma unroll
        for (int i = 0; i < CPL; i++) {
            int c = lane * CPL + i;
            g_carry[((c * Bn + b) * 4 + sk) * D4n + sd4] =
                make_float2(Cre, Cim);
            float nre = fmaf(rLre, Cre, fmaf(-rLim, Cim, e[i].x));
            float nim = fmaf(rLre, Cim, fmaf(rLim, Cre, e[i].y));
            Cre = nre; Cim = nim;
        }
    }

    gsync(1);

    // -------- phase 3: replay with carry; reverse rounds so x is L2-hot --------
#pragma unroll 1
    for (int round = 1; round >= 0; round--) {
        const int item = round * NTH + t;
        const int b = (item / D4n) % Bn;
        const int c = item / (D4n * Bn);

        float zre[4], zim[4];
#pragma unroll
        for (int k = 0; k < 4; k++) {
            float2 cc = g_carry[((c * Bn + b) * 4 + k) * D4n + d4];
            zre[k] = cc.x;
            zim[k] = cc.y;
        }

        const float4* xp = x + (size_t)(b * Tn + c * Ln) * D4n + d4;
        float4*       yp = y + (size_t)(b * Tn + c * Ln) * D4n + d4;
#pragma unroll 8
        for (int j = 0; j < Ln; j++) {
            float4 xv = xp[(size_t)j * D4n];
            float xr[4] = {xv.x, xv.y, xv.z, xv.w};
#pragma unroll
            for (int k = 0; k < 4; k++) {
                float nre = fmaf(rre[k], zre[k], fmaf(-rim[k], zim[k], xr[k]));
                float nim = fmaf(rre[k], zim[k], rim[k] * zre[k]);
                zre[k] = nre;
                zim[k] = nim;
            }
            __stcs(&yp[(size_t)j * D4n],
                   make_float4(zre[0], zre[1], zre[2], zre[3]));
        }
    }
}

// ---------------------------------------------------------------------------
extern "C" void kernel_launch(void* const* d_in, const int* in_sizes, int n_in,
                              void* d_out, int out_size)
{
    const float* x     = (const float*)d_in[0];
    const float* decay = (const float*)d_in[1];
    const float* freq  = (const float*)d_in[2];
    float* y = (float*)d_out;

    k_fused<<<GRID_CTAS, 256>>>((const float4*)x, (float4*)y, decay, freq);
}